// round 13
// baseline (speedup 1.0000x reference)
#include <cuda_runtime.h>
#include <math.h>

#define NT 256
typedef unsigned long long ull;

// Shared layout (float offsets)
#define OFF_NT    0        // nodeT [32 feat][32 node] stride 33 = 1056
#define OFF_H     1056     // [32][65] = 2080
#define OFF_MI    3136     // [32][36] = 1152
#define OFF_EDGE  4288     // [992][2] = 1984
#define OFF_BASE  6272     // [32][68] = 2176 (stride 68 -> 16B aligned rows)
#define OFF_PROJ  8448     // [32][68] = 2176
#define OFF_A     10624    // staging W2a[0:64]+b2a (4160) / readout t1 (2176)
#define OFF_W2B2  14784    // W2b: 2048 floats
#define OFF_W2C2  16832    // wCt paired-transposed W2c: 512 ull = 1024 floats
#define OFF_W45S  17856    // w45 interleaved: 128 floats
#define OFF_B2B   17984    // 32
#define OFF_B2C   18016    // 32
#define SMEM_FLOATS 18048  // 72,192 B -> 2 CTAs/SM

__device__ __forceinline__ float rcp_fast(float x) {
    float r; asm("rcp.approx.f32 %0, %1;" : "=f"(r) : "f"(x)); return r;
}
__device__ __forceinline__ float ex2_fast(float x) {
    float r; asm("ex2.approx.f32 %0, %1;" : "=f"(r) : "f"(x)); return r;
}
__device__ __forceinline__ ull pack2(float lo, float hi) {
    ull r; asm("mov.b64 %0, {%1, %2};" : "=l"(r) : "f"(lo), "f"(hi)); return r;
}
__device__ __forceinline__ ull dup2(float x) { return pack2(x, x); }
__device__ __forceinline__ void unpack2(ull v, float& lo, float& hi) {
    asm("mov.b64 {%0, %1}, %2;" : "=f"(lo), "=f"(hi) : "l"(v));
}
__device__ __forceinline__ ull fma2(ull a, ull b, ull c) {
    ull d; asm("fma.rn.f32x2 %0, %1, %2, %3;" : "=l"(d) : "l"(a), "l"(b), "l"(c));
    return d;
}
__device__ __forceinline__ ull add2(ull a, ull b) {
    ull d; asm("add.rn.f32x2 %0, %1, %2;" : "=l"(d) : "l"(a), "l"(b));
    return d;
}
__device__ __forceinline__ ull mul2(ull a, ull b) {
    ull d; asm("mul.rn.f32x2 %0, %1, %2;" : "=l"(d) : "l"(a), "l"(b));
    return d;
}

// Packed GELU on an f32x2 pair: A&S 7.1.26 erf; poly on FMA pipe, 2 RCP + 2 EX2 on MUFU.
__device__ __forceinline__ ull gelu2(ull x2) {
    ull s2 = mul2(x2, dup2(0.7071067811865476f));
    ull a2 = s2 & 0x7FFFFFFF7FFFFFFFULL;
    ull v2 = fma2(a2, dup2(0.3275911f), dup2(1.0f));
    float v0, v1; unpack2(v2, v0, v1);
    ull r2 = pack2(rcp_fast(v0), rcp_fast(v1));
    ull u2 = mul2(a2, a2);
    ull y2 = mul2(u2, dup2(-1.4426950408889634f));
    float y0, y1; unpack2(y2, y0, y1);
    ull e2 = pack2(ex2_fast(y0), ex2_fast(y1));
    ull q2 = dup2(1.061405429f);
    q2 = fma2(q2, r2, dup2(-1.453152027f));
    q2 = fma2(q2, r2, dup2(1.421413741f));
    q2 = fma2(q2, r2, dup2(-0.284496736f));
    q2 = fma2(q2, r2, dup2(0.254829592f));
    q2 = mul2(q2, r2);
    ull t2 = mul2(q2, e2);
    ull E2 = fma2(t2, dup2(-1.0f), dup2(1.0f));
    E2 = E2 | (s2 & 0x8000000080000000ULL);
    ull hx = mul2(x2, dup2(0.5f));
    return fma2(hx, E2, hx);
}
__device__ __forceinline__ float sigm_f(float x) {
    return rcp_fast(1.0f + ex2_fast(-x * 1.4426950408889634f));
}

struct GnnParams {
    const float *node0, *edge, *h0, *mean, *vari;
    const int   *iterp;
    const float *W1a, *b1a, *W2a, *b2a, *W2b, *b2b, *W2c, *b2c;
    const float *Wih, *Whh, *bih, *bhh, *W3b, *b3b;
    const float *W4a, *b4a, *W4b, *b4b, *W4c, *b4c, *W5a, *b5a, *W5b, *b5b;
    float *out;
};

__global__ __launch_bounds__(NT, 2)
void gnn_kernel(GnnParams p) {
    extern __shared__ float sm[];
    const int tid  = threadIdx.x;
    const int b    = blockIdx.x;
    const int warp = tid >> 5, lane = tid & 31;

    float* sNT   = sm + OFF_NT;
    float* sH    = sm + OFF_H;     // stride 65
    float* sMi   = sm + OFF_MI;    // stride 36
    float* sEdge = sm + OFF_EDGE;
    float* sBase = sm + OFF_BASE;  // stride 68
    float* sProj = sm + OFF_PROJ;  // stride 68
    float* bufA  = sm + OFF_A;
    const ull*   wB   = (const ull*)(sm + OFF_W2B2);
    const ull*   wCt  = (const ull*)(sm + OFF_W2C2);
    const float* w45x = sm + OFF_W45S;
    const ull*   bB   = (const ull*)(sm + OFF_B2B);
    const float* bCs  = sm + OFF_B2C;

    // ---- init copies (once) ----
    for (int i = tid; i < 992*2; i += NT) sEdge[i] = p.edge[b*1984 + i];
    for (int i = tid; i < 32*64; i += NT) {
        int n = i >> 6, k = i & 63;
        sH[n*65 + k] = p.h0[b*2048 + i];
    }
    for (int i = tid; i < 2048;  i += NT) sm[OFF_W2B2 + i] = p.W2b[i];
    for (int i = tid; i < 512;   i += NT) {
        int c = i >> 4, qp = i & 15;
        ((ull*)(sm + OFF_W2C2))[i] =
            pack2(p.W2c[(2*qp)*32 + c], p.W2c[(2*qp+1)*32 + c]);
    }
    for (int i = tid; i < 128;   i += NT) {
        int t = i >> 2, sub = i & 3;
        int src = (sub < 2) ? (64*64 + 2*t + sub) : (64*64 + 64 + 2*t + (sub - 2));
        sm[OFF_W45S + i] = p.W2a[src];
    }
    for (int i = tid; i < 32;    i += NT) {
        sm[OFF_B2B + i] = p.b2b[i];
        sm[OFF_B2C + i] = p.b2c[i];
    }
    if (tid < 32) {
        sMi[tid*36 + 32] = p.mean[b*32 + tid];
        sMi[tid*36 + 33] = 1.0f / p.vari[b*32 + tid];
    }
    for (int i = tid; i < 1024; i += NT) sBase[i] = p.node0[b*1024 + i];
    for (int i = tid; i < 4096; i += NT) bufA[i] = p.W2a[i];
    for (int i = tid + 4096; i < 4160; i += NT) bufA[i] = p.b2a[i - 4096];
    __syncthreads();

    // ---- node = node0 @ W1a + b1a (write transposed into sNT) ----
    {
        const int n = tid >> 3, f0 = (tid & 7) << 2;
        float a0 = p.b1a[f0], a1 = p.b1a[f0+1], a2 = p.b1a[f0+2], a3 = p.b1a[f0+3];
        const float* r = sBase + n*32;
        #pragma unroll 8
        for (int k = 0; k < 32; ++k) {
            float a = r[k];
            float4 w = *(const float4*)(p.W1a + k*32 + f0);
            a0 += a*w.x; a1 += a*w.y; a2 += a*w.z; a3 += a*w.w;
        }
        sNT[(f0+0)*33 + n] = a0; sNT[(f0+1)*33 + n] = a1;
        sNT[(f0+2)*33 + n] = a2; sNT[(f0+3)*33 + n] = a3;
    }
    __syncthreads();

    const int iters = p.iterp ? *p.iterp : 3;

    for (int it = 0; it < iters; ++it) {
        // ---- base = node@W2a[0:32]+b2a ; proj = node@W2a[32:64] ----
        {
            const int n = tid >> 3, c0 = (tid & 7) << 3;
            ull bacc[4], pacc[4];
            {
                ulonglong2 b0 = *(const ulonglong2*)(bufA + 4096 + c0);
                ulonglong2 b1 = *(const ulonglong2*)(bufA + 4096 + c0 + 4);
                bacc[0]=b0.x; bacc[1]=b0.y; bacc[2]=b1.x; bacc[3]=b1.y;
            }
            const ull z = dup2(0.0f);
            #pragma unroll
            for (int o = 0; o < 4; ++o) pacc[o] = z;
            #pragma unroll 4
            for (int k = 0; k < 32; ++k) {
                ull aa = dup2(sNT[k*33 + n]);
                ulonglong2 wb0 = *(const ulonglong2*)(bufA + k*64 + c0);
                ulonglong2 wb1 = *(const ulonglong2*)(bufA + k*64 + c0 + 4);
                ulonglong2 wp0 = *(const ulonglong2*)(bufA + (32+k)*64 + c0);
                ulonglong2 wp1 = *(const ulonglong2*)(bufA + (32+k)*64 + c0 + 4);
                bacc[0] = fma2(aa, wb0.x, bacc[0]); bacc[1] = fma2(aa, wb0.y, bacc[1]);
                bacc[2] = fma2(aa, wb1.x, bacc[2]); bacc[3] = fma2(aa, wb1.y, bacc[3]);
                pacc[0] = fma2(aa, wp0.x, pacc[0]); pacc[1] = fma2(aa, wp0.y, pacc[1]);
                pacc[2] = fma2(aa, wp1.x, pacc[2]); pacc[3] = fma2(aa, wp1.y, pacc[3]);
            }
            *(ulonglong2*)(sBase + n*68 + c0)     = make_ulonglong2(bacc[0], bacc[1]);
            *(ulonglong2*)(sBase + n*68 + c0 + 4) = make_ulonglong2(bacc[2], bacc[3]);
            *(ulonglong2*)(sProj + n*68 + c0)     = make_ulonglong2(pacc[0], pacc[1]);
            *(ulonglong2*)(sProj + n*68 + c0 + 4) = make_ulonglong2(pacc[2], pacc[3]);
        }
        __syncthreads();

        // ---- edge phase: 2 passes, each warp handles TWO nodes (iA, iB);
        //      lane = edge q of each; W2b sweep shared between the two edges ----
        for (int pass = 0; pass < 2; ++pass) {
            const int iA = pass * 16 + warp;
            const int iB = iA + 8;
            const int q  = (lane < 31) ? lane : 30;
            const int jA = q + (q >= iA);
            const int jB = q + (q >= iB);
            ull evA = *(const ull*)(sEdge + (iA*31 + q)*2);
            ull evB = *(const ull*)(sEdge + (iB*31 + q)*2);
            float eA0, eA1, eB0, eB1;
            unpack2(evA, eA0, eA1); unpack2(evB, eB0, eB1);
            const ull e0dA = dup2(eA0), e1dA = dup2(eA1);
            const ull e0dB = dup2(eB0), e1dB = dup2(eB1);
            const float* prjA = sProj + jA*68;
            const float* prjB = sProj + jB*68;
            const float* basA = sBase + iA*68;
            const float* basB = sBase + iB*68;

            ull accA[16], accB[16];
            #pragma unroll
            for (int cp = 0; cp < 16; ++cp) { accA[cp] = bB[cp]; accB[cp] = bB[cp]; }

            #pragma unroll 2
            for (int tp = 0; tp < 16; ++tp) {
                ulonglong2 bpA = *(const ulonglong2*)(basA + 4*tp);
                ulonglong2 bpB = *(const ulonglong2*)(basB + 4*tp);
                ulonglong2 ppA = *(const ulonglong2*)(prjA + 4*tp);
                ulonglong2 ppB = *(const ulonglong2*)(prjB + 4*tp);
                ulonglong2 wa  = *(const ulonglong2*)(w45x + 8*tp);
                ulonglong2 wbv = *(const ulonglong2*)(w45x + 8*tp + 4);
                ull uA0 = fma2(e1dA, wa.y,  fma2(e0dA, wa.x,  add2(bpA.x, ppA.x)));
                ull uA1 = fma2(e1dA, wbv.y, fma2(e0dA, wbv.x, add2(bpA.y, ppA.y)));
                ull uB0 = fma2(e1dB, wa.y,  fma2(e0dB, wa.x,  add2(bpB.x, ppB.x)));
                ull uB1 = fma2(e1dB, wbv.y, fma2(e0dB, wbv.x, add2(bpB.y, ppB.y)));
                ull gA0 = gelu2(uA0), gA1 = gelu2(uA1);
                ull gB0 = gelu2(uB0), gB1 = gelu2(uB1);
                float a0s, a1s, a2s, a3s, b0s, b1s, b2s, b3s;
                unpack2(gA0, a0s, a1s); unpack2(gA1, a2s, a3s);
                unpack2(gB0, b0s, b1s); unpack2(gB1, b2s, b3s);
                ull A0 = dup2(a0s), A1 = dup2(a1s), A2 = dup2(a2s), A3 = dup2(a3s);
                ull B0 = dup2(b0s), B1 = dup2(b1s), B2 = dup2(b2s), B3 = dup2(b3s);
                const int k0 = 4*tp;
                #pragma unroll
                for (int cp2 = 0; cp2 < 8; ++cp2) {
                    ulonglong2 w0 = *(const ulonglong2*)(wB + (k0+0)*16 + 2*cp2);
                    ulonglong2 w1 = *(const ulonglong2*)(wB + (k0+1)*16 + 2*cp2);
                    ulonglong2 w2 = *(const ulonglong2*)(wB + (k0+2)*16 + 2*cp2);
                    ulonglong2 w3 = *(const ulonglong2*)(wB + (k0+3)*16 + 2*cp2);
                    accA[2*cp2]   = fma2(A0, w0.x, accA[2*cp2]);
                    accA[2*cp2+1] = fma2(A0, w0.y, accA[2*cp2+1]);
                    accB[2*cp2]   = fma2(B0, w0.x, accB[2*cp2]);
                    accB[2*cp2+1] = fma2(B0, w0.y, accB[2*cp2+1]);
                    accA[2*cp2]   = fma2(A1, w1.x, accA[2*cp2]);
                    accA[2*cp2+1] = fma2(A1, w1.y, accA[2*cp2+1]);
                    accB[2*cp2]   = fma2(B1, w1.x, accB[2*cp2]);
                    accB[2*cp2+1] = fma2(B1, w1.y, accB[2*cp2+1]);
                    accA[2*cp2]   = fma2(A2, w2.x, accA[2*cp2]);
                    accA[2*cp2+1] = fma2(A2, w2.y, accA[2*cp2+1]);
                    accB[2*cp2]   = fma2(B2, w2.x, accB[2*cp2]);
                    accB[2*cp2+1] = fma2(B2, w2.y, accB[2*cp2+1]);
                    accA[2*cp2]   = fma2(A3, w3.x, accA[2*cp2]);
                    accA[2*cp2+1] = fma2(A3, w3.y, accA[2*cp2+1]);
                    accB[2*cp2]   = fma2(B3, w3.x, accB[2*cp2]);
                    accB[2*cp2+1] = fma2(B3, w3.y, accB[2*cp2+1]);
                }
            }

            // gelu m2 in place (packed)
            #pragma unroll
            for (int cp = 0; cp < 16; ++cp) {
                accA[cp] = gelu2(accA[cp]);
                accB[cp] = gelu2(accB[cp]);
            }

            const ull mask2 = dup2((lane < 31) ? 1.0f : 0.0f);

            // layer 3 + butterfly for each edge (A then B; keeps regs < 128)
            #pragma unroll
            for (int side = 0; side < 2; ++side) {
                const ull* accp = side ? accB : accA;
                const int  inode = side ? iB : iA;
                float m3[32];
                #pragma unroll
                for (int c2 = 0; c2 < 16; ++c2) {
                    float b0, b1;
                    {
                        ull bc = *(const ull*)(bCs + 2*c2);
                        unpack2(bc, b0, b1);
                    }
                    ull s0a = pack2(b0, 0.0f), s0b = dup2(0.0f);
                    ull s1a = pack2(b1, 0.0f), s1b = dup2(0.0f);
                    const ull* wr0 = wCt + (2*c2)*16;
                    const ull* wr1 = wCt + (2*c2+1)*16;
                    #pragma unroll
                    for (int jj = 0; jj < 8; ++jj) {
                        ulonglong2 w0 = *(const ulonglong2*)(wr0 + 2*jj);
                        ulonglong2 w1 = *(const ulonglong2*)(wr1 + 2*jj);
                        s0a = fma2(accp[2*jj],   w0.x, s0a);
                        s0b = fma2(accp[2*jj+1], w0.y, s0b);
                        s1a = fma2(accp[2*jj],   w1.x, s1a);
                        s1b = fma2(accp[2*jj+1], w1.y, s1b);
                    }
                    s0a = add2(s0a, s0b);
                    s1a = add2(s1a, s1b);
                    float l0, h0, l1, h1;
                    unpack2(s0a, l0, h0); unpack2(s1a, l1, h1);
                    ull g = gelu2(pack2(l0 + h0, l1 + h1));
                    g = mul2(g, mask2);
                    unpack2(g, m3[2*c2], m3[2*c2+1]);
                }
                #pragma unroll
                for (int s = 0; s < 5; ++s) {
                    const int off = 1 << s;
                    const int h = 16 >> s;
                    const bool keep_low = ((lane >> s) & 1) == 0;
                    #pragma unroll
                    for (int r = 0; r < 16; ++r) {
                        if (r < h) {
                            float send = keep_low ? m3[r + h] : m3[r];
                            float recv = __shfl_xor_sync(0xffffffffu, send, off);
                            float mine = keep_low ? m3[r] : m3[r + h];
                            m3[r] = mine + recv;
                        }
                    }
                }
                const int e = ((lane & 1) << 4) | (((lane >> 1) & 1) << 3) |
                              (((lane >> 2) & 1) << 2) | (((lane >> 3) & 1) << 1) |
                              ((lane >> 4) & 1);
                sMi[inode*36 + e] = m3[0];
            }
        }
        __syncthreads();

        // ---- GRU cell (GELU new gate), packed col-pairs ----
        {
            const int n  = tid >> 3;
            const int c0 = (tid & 7) << 3;
            ull ar[4], az[4], an_[4], hn_[4];
            #pragma unroll
            for (int o = 0; o < 4; ++o) {
                ull bi_r = *(const ull*)(p.bih + c0 + 2*o);
                ull bh_r = *(const ull*)(p.bhh + c0 + 2*o);
                ull bi_z = *(const ull*)(p.bih + 64 + c0 + 2*o);
                ull bh_z = *(const ull*)(p.bhh + 64 + c0 + 2*o);
                ar[o]  = add2(bi_r, bh_r);
                az[o]  = add2(bi_z, bh_z);
                an_[o] = *(const ull*)(p.bih + 128 + c0 + 2*o);
                hn_[o] = *(const ull*)(p.bhh + 128 + c0 + 2*o);
            }
            const float* mi = sMi + n*36;
            #pragma unroll 2
            for (int k = 0; k < 34; ++k) {
                ull aa = dup2(mi[k]);
                const float* w = p.Wih + k*192;
                ulonglong2 r01 = *(const ulonglong2*)(w + c0);
                ulonglong2 r23 = *(const ulonglong2*)(w + c0 + 4);
                ulonglong2 z01 = *(const ulonglong2*)(w + 64 + c0);
                ulonglong2 z23 = *(const ulonglong2*)(w + 64 + c0 + 4);
                ulonglong2 n01 = *(const ulonglong2*)(w + 128 + c0);
                ulonglong2 n23 = *(const ulonglong2*)(w + 128 + c0 + 4);
                ar[0]=fma2(aa,r01.x,ar[0]); ar[1]=fma2(aa,r01.y,ar[1]);
                ar[2]=fma2(aa,r23.x,ar[2]); ar[3]=fma2(aa,r23.y,ar[3]);
                az[0]=fma2(aa,z01.x,az[0]); az[1]=fma2(aa,z01.y,az[1]);
                az[2]=fma2(aa,z23.x,az[2]); az[3]=fma2(aa,z23.y,az[3]);
                an_[0]=fma2(aa,n01.x,an_[0]); an_[1]=fma2(aa,n01.y,an_[1]);
                an_[2]=fma2(aa,n23.x,an_[2]); an_[3]=fma2(aa,n23.y,an_[3]);
            }
            const float* hv = sH + n*65;
            #pragma unroll 2
            for (int k = 0; k < 64; ++k) {
                ull aa = dup2(hv[k]);
                const float* w = p.Whh + k*192;
                ulonglong2 r01 = *(const ulonglong2*)(w + c0);
                ulonglong2 r23 = *(const ulonglong2*)(w + c0 + 4);
                ulonglong2 z01 = *(const ulonglong2*)(w + 64 + c0);
                ulonglong2 z23 = *(const ulonglong2*)(w + 64 + c0 + 4);
                ulonglong2 n01 = *(const ulonglong2*)(w + 128 + c0);
                ulonglong2 n23 = *(const ulonglong2*)(w + 128 + c0 + 4);
                ar[0]=fma2(aa,r01.x,ar[0]); ar[1]=fma2(aa,r01.y,ar[1]);
                ar[2]=fma2(aa,r23.x,ar[2]); ar[3]=fma2(aa,r23.y,ar[3]);
                az[0]=fma2(aa,z01.x,az[0]); az[1]=fma2(aa,z01.y,az[1]);
                az[2]=fma2(aa,z23.x,az[2]); az[3]=fma2(aa,z23.y,az[3]);
                hn_[0]=fma2(aa,n01.x,hn_[0]); hn_[1]=fma2(aa,n01.y,hn_[1]);
                hn_[2]=fma2(aa,n23.x,hn_[2]); hn_[3]=fma2(aa,n23.y,hn_[3]);
            }
            float hnew[8];
            #pragma unroll
            for (int o = 0; o < 4; ++o) {
                float r0, r1, z0, z1, in0, in1, hn0, hn1;
                unpack2(ar[o], r0, r1);
                unpack2(az[o], z0, z1);
                unpack2(an_[o], in0, in1);
                unpack2(hn_[o], hn0, hn1);
                float rr0 = sigm_f(r0), rr1 = sigm_f(r1);
                float zz0 = sigm_f(z0), zz1 = sigm_f(z1);
                float g0, g1;
                unpack2(gelu2(pack2(fmaf(rr0, hn0, in0), fmaf(rr1, hn1, in1))), g0, g1);
                hnew[2*o]   = (1.0f - zz0) * g0 + zz0 * hv[c0 + 2*o];
                hnew[2*o+1] = (1.0f - zz1) * g1 + zz1 * hv[c0 + 2*o + 1];
            }
            __syncthreads();
            #pragma unroll
            for (int o = 0; o < 8; ++o) sH[n*65 + c0 + o] = hnew[o];
        }
        __syncthreads();

        // ---- node = h @ W3b + b3b  (packed, write transposed into sNT) ----
        {
            const int n = tid >> 3, f0 = (tid & 7) << 2;
            ull a01 = *(const ull*)(p.b3b + f0);
            ull a23 = *(const ull*)(p.b3b + f0 + 2);
            const float* hv = sH + n*65;
            #pragma unroll 4
            for (int k = 0; k < 64; ++k) {
                ull aa = dup2(hv[k]);
                ulonglong2 w2 = *(const ulonglong2*)(p.W3b + k*32 + f0);
                a01 = fma2(aa, w2.x, a01);
                a23 = fma2(aa, w2.y, a23);
            }
            float v0, v1, v2, v3;
            unpack2(a01, v0, v1); unpack2(a23, v2, v3);
            sNT[(f0+0)*33 + n] = v0; sNT[(f0+1)*33 + n] = v1;
            sNT[(f0+2)*33 + n] = v2; sNT[(f0+3)*33 + n] = v3;
        }
        __syncthreads();
    }

    // ---- readout (scratch: bufA=t1, sBase=t2, sProj=t3, sBase=t4) ----
    {   // t1 = node @ W4a + b4a : [32][68]
        const int n = tid >> 3, f0 = (tid & 7) << 3;
        ull acc[4];
        acc[0] = *(const ull*)(p.b4a + f0);
        acc[1] = *(const ull*)(p.b4a + f0 + 2);
        acc[2] = *(const ull*)(p.b4a + f0 + 4);
        acc[3] = *(const ull*)(p.b4a + f0 + 6);
        #pragma unroll 4
        for (int k = 0; k < 32; ++k) {
            ull aa = dup2(sNT[k*33 + n]);
            ulonglong2 w0 = *(const ulonglong2*)(p.W4a + k*64 + f0);
            ulonglong2 w1 = *(const ulonglong2*)(p.W4a + k*64 + f0 + 4);
            acc[0] = fma2(aa, w0.x, acc[0]); acc[1] = fma2(aa, w0.y, acc[1]);
            acc[2] = fma2(aa, w1.x, acc[2]); acc[3] = fma2(aa, w1.y, acc[3]);
        }
        *(ulonglong2*)(bufA + n*68 + f0)     = make_ulonglong2(acc[0], acc[1]);
        *(ulonglong2*)(bufA + n*68 + f0 + 4) = make_ulonglong2(acc[2], acc[3]);
    }
    __syncthreads();
    {   // t2 = t1 @ W4b + b4b : [32][36] into sBase
        const int n = tid >> 3, f0 = (tid & 7) << 2;
        ull a01 = *(const ull*)(p.b4b + f0);
        ull a23 = *(const ull*)(p.b4b + f0 + 2);
        const float* r = bufA + n*68;
        #pragma unroll 4
        for (int k = 0; k < 64; ++k) {
            ull aa = dup2(r[k]);
            ulonglong2 w2 = *(const ulonglong2*)(p.W4b + k*32 + f0);
            a01 = fma2(aa, w2.x, a01);
            a23 = fma2(aa, w2.y, a23);
        }
        *(ull*)(sBase + n*36 + f0)     = a01;
        *(ull*)(sBase + n*36 + f0 + 2) = a23;
    }
    __syncthreads();
    {   // t3 = t2 @ W4c + b4c : [32][36] into sProj
        const int n = tid >> 3, f0 = (tid & 7) << 2;
        ull a01 = *(const ull*)(p.b4c + f0);
        ull a23 = *(const ull*)(p.b4c + f0 + 2);
        const float* r = sBase + n*36;
        #pragma unroll 4
        for (int k = 0; k < 32; ++k) {
            ull aa = dup2(r[k]);
            ulonglong2 w2 = *(const ulonglong2*)(p.W4c + k*32 + f0);
            a01 = fma2(aa, w2.x, a01);
            a23 = fma2(aa, w2.y, a23);
        }
        *(ull*)(sProj + n*36 + f0)     = a01;
        *(ull*)(sProj + n*36 + f0 + 2) = a23;
    }
    __syncthreads();
    {   // t4 = t3 @ W5a + b5a : [32][18] into sBase
        const int n = tid >> 3, f0 = (tid & 7) << 1;
        float a0 = p.b5a[f0], a1 = p.b5a[f0 + 1];
        const float* r = sProj + n*36;
        #pragma unroll 8
        for (int k = 0; k < 32; ++k) {
            float a = r[k];
            a0 += a * p.W5a[k*16 + f0];
            a1 += a * p.W5a[k*16 + f0 + 1];
        }
        sBase[n*18 + f0]     = a0;
        sBase[n*18 + f0 + 1] = a1;
    }
    __syncthreads();
    if (tid < 64) {
        const int n = tid >> 1, col = tid & 1;
        float acc = p.b5b[col];
        const float* r = sBase + n*18;
        #pragma unroll
        for (int k = 0; k < 16; ++k) acc += r[k] * p.W5b[k*2 + col];
        if (col == 0) p.out[b*32 + n] = acc;
        else          p.out[32768 + b*32 + n] = 1.0f / acc;
    }
}

extern "C" void kernel_launch(void* const* d_in, const int* in_sizes, int n_in,
                              void* d_out, int out_size) {
    const int has_iter = (n_in >= 32) ? 1 : 0;
    const int base = has_iter ? 8 : 7;

    GnnParams p;
    p.node0 = (const float*)d_in[0];
    p.edge  = (const float*)d_in[1];
    p.h0    = (const float*)d_in[2];
    p.mean  = (const float*)d_in[3];
    p.vari  = (const float*)d_in[4];
    p.iterp = has_iter ? (const int*)d_in[7] : nullptr;
    p.W1a = (const float*)d_in[base+0];  p.b1a = (const float*)d_in[base+1];
    p.W2a = (const float*)d_in[base+2];  p.b2a = (const float*)d_in[base+3];
    p.W2b = (const float*)d_in[base+4];  p.b2b = (const float*)d_in[base+5];
    p.W2c = (const float*)d_in[base+6];  p.b2c = (const float*)d_in[base+7];
    p.Wih = (const float*)d_in[base+8];  p.Whh = (const float*)d_in[base+9];
    p.bih = (const float*)d_in[base+10]; p.bhh = (const float*)d_in[base+11];
    p.W3b = (const float*)d_in[base+12]; p.b3b = (const float*)d_in[base+13];
    p.W4a = (const float*)d_in[base+14]; p.b4a = (const float*)d_in[base+15];
    p.W4b = (const float*)d_in[base+16]; p.b4b = (const float*)d_in[base+17];
    p.W4c = (const float*)d_in[base+18]; p.b4c = (const float*)d_in[base+19];
    p.W5a = (const float*)d_in[base+20]; p.b5a = (const float*)d_in[base+21];
    p.W5b = (const float*)d_in[base+22]; p.b5b = (const float*)d_in[base+23];
    p.out = (float*)d_out;

    cudaFuncSetAttribute(gnn_kernel,
                         cudaFuncAttributeMaxDynamicSharedMemorySize,
                         SMEM_FLOATS * (int)sizeof(float));
    gnn_kernel<<<1024, NT, SMEM_FLOATS * sizeof(float)>>>(p);
}

// round 14
// speedup vs baseline: 4.1474x; 4.1474x over previous
#include <cuda_runtime.h>
#include <math.h>

#define NT 256
typedef unsigned long long ull;

// Shared layout (float offsets)
#define OFF_NT    0        // nodeT [32 feat][32 node] stride 33 = 1056
#define OFF_H     1056     // [32][65] = 2080
#define OFF_MI    3136     // [32][36] = 1152
#define OFF_EDGE  4288     // [992][2] = 1984
#define OFF_BASE  6272     // [32][68] = 2176 (stride 68 -> 16B aligned rows)
#define OFF_PROJ  8448     // [32][68] = 2176
#define OFF_A     10624    // staging W2a[0:64]+b2a (4160) / readout t1 (2176)
#define OFF_W2B   14784    // W2b plain [64][32]: 2048 floats
#define OFF_WCTR  16832    // W2c transposed [c][k]: 1024 floats
#define OFF_W45   17856    // W2a row64 (64) then row65 (64): 128 floats
#define OFF_B2B   17984    // 32
#define OFF_B2C   18016    // 32
#define SMEM_FLOATS 18048  // 72,192 B -> 2 CTAs/SM

__device__ __forceinline__ float rcp_fast(float x) {
    float r; asm("rcp.approx.f32 %0, %1;" : "=f"(r) : "f"(x)); return r;
}
__device__ __forceinline__ float ex2_fast(float x) {
    float r; asm("ex2.approx.f32 %0, %1;" : "=f"(r) : "f"(x)); return r;
}
__device__ __forceinline__ ull pack2(float lo, float hi) {
    ull r; asm("mov.b64 %0, {%1, %2};" : "=l"(r) : "f"(lo), "f"(hi)); return r;
}
__device__ __forceinline__ ull dup2(float x) { return pack2(x, x); }
__device__ __forceinline__ void unpack2(ull v, float& lo, float& hi) {
    asm("mov.b64 {%0, %1}, %2;" : "=f"(lo), "=f"(hi) : "l"(v));
}
__device__ __forceinline__ ull fma2(ull a, ull b, ull c) {
    ull d; asm("fma.rn.f32x2 %0, %1, %2, %3;" : "=l"(d) : "l"(a), "l"(b), "l"(c));
    return d;
}
__device__ __forceinline__ ull add2(ull a, ull b) {
    ull d; asm("add.rn.f32x2 %0, %1, %2;" : "=l"(d) : "l"(a), "l"(b));
    return d;
}
__device__ __forceinline__ ull mul2(ull a, ull b) {
    ull d; asm("mul.rn.f32x2 %0, %1, %2;" : "=l"(d) : "l"(a), "l"(b));
    return d;
}
__device__ __forceinline__ ull shflxor64(ull v, int m) {
    unsigned lo = (unsigned)v, hi = (unsigned)(v >> 32);
    lo = __shfl_xor_sync(0xffffffffu, lo, m);
    hi = __shfl_xor_sync(0xffffffffu, hi, m);
    return ((ull)hi << 32) | lo;
}

// Packed GELU on an f32x2 pair: A&S 7.1.26 erf; poly on FMA pipe, 2 RCP + 2 EX2 on MUFU.
__device__ __forceinline__ ull gelu2(ull x2) {
    ull s2 = mul2(x2, dup2(0.7071067811865476f));
    ull a2 = s2 & 0x7FFFFFFF7FFFFFFFULL;
    ull v2 = fma2(a2, dup2(0.3275911f), dup2(1.0f));
    float v0, v1; unpack2(v2, v0, v1);
    ull r2 = pack2(rcp_fast(v0), rcp_fast(v1));
    ull u2 = mul2(a2, a2);
    ull y2 = mul2(u2, dup2(-1.4426950408889634f));
    float y0, y1; unpack2(y2, y0, y1);
    ull e2 = pack2(ex2_fast(y0), ex2_fast(y1));
    ull q2 = dup2(1.061405429f);
    q2 = fma2(q2, r2, dup2(-1.453152027f));
    q2 = fma2(q2, r2, dup2(1.421413741f));
    q2 = fma2(q2, r2, dup2(-0.284496736f));
    q2 = fma2(q2, r2, dup2(0.254829592f));
    q2 = mul2(q2, r2);
    ull t2 = mul2(q2, e2);
    ull E2 = fma2(t2, dup2(-1.0f), dup2(1.0f));
    E2 = E2 | (s2 & 0x8000000080000000ULL);
    ull hx = mul2(x2, dup2(0.5f));
    return fma2(hx, E2, hx);
}
__device__ __forceinline__ float sigm_f(float x) {
    return rcp_fast(1.0f + ex2_fast(-x * 1.4426950408889634f));
}

struct GnnParams {
    const float *node0, *edge, *h0, *mean, *vari;
    const int   *iterp;
    const float *W1a, *b1a, *W2a, *b2a, *W2b, *b2b, *W2c, *b2c;
    const float *Wih, *Whh, *bih, *bhh, *W3b, *b3b;
    const float *W4a, *b4a, *W4b, *b4b, *W4c, *b4c, *W5a, *b5a, *W5b, *b5b;
    float *out;
};

__global__ __launch_bounds__(NT, 2)
void gnn_kernel(GnnParams p) {
    extern __shared__ float sm[];
    const int tid  = threadIdx.x;
    const int b    = blockIdx.x;
    const int warp = tid >> 5, lane = tid & 31;

    float* sNT   = sm + OFF_NT;
    float* sH    = sm + OFF_H;     // stride 65
    float* sMi   = sm + OFF_MI;    // stride 36
    float* sEdge = sm + OFF_EDGE;
    float* sBase = sm + OFF_BASE;  // stride 68
    float* sProj = sm + OFF_PROJ;  // stride 68
    float* bufA  = sm + OFF_A;
    const float* W2bs = sm + OFF_W2B;
    const float* wCtr = sm + OFF_WCTR;
    const float* w45x = sm + OFF_W45;
    const float* bBs  = sm + OFF_B2B;
    const float* bCs  = sm + OFF_B2C;

    // ---- init copies (once) ----
    for (int i = tid; i < 992*2; i += NT) sEdge[i] = p.edge[b*1984 + i];
    for (int i = tid; i < 32*64; i += NT) {
        int n = i >> 6, k = i & 63;
        sH[n*65 + k] = p.h0[b*2048 + i];
    }
    for (int i = tid; i < 2048;  i += NT) sm[OFF_W2B + i] = p.W2b[i];
    for (int i = tid; i < 1024;  i += NT) {    // wCtr[c][k] = W2c[k][c]
        int c = i >> 5, k = i & 31;
        sm[OFF_WCTR + i] = p.W2c[k*32 + c];
    }
    for (int i = tid; i < 128;   i += NT) sm[OFF_W45 + i] = p.W2a[64*64 + i];
    for (int i = tid; i < 32;    i += NT) {
        sm[OFF_B2B + i] = p.b2b[i];
        sm[OFF_B2C + i] = p.b2c[i];
    }
    if (tid < 32) {
        sMi[tid*36 + 32] = p.mean[b*32 + tid];
        sMi[tid*36 + 33] = 1.0f / p.vari[b*32 + tid];
    }
    for (int i = tid; i < 1024; i += NT) sBase[i] = p.node0[b*1024 + i];
    for (int i = tid; i < 4096; i += NT) bufA[i] = p.W2a[i];
    for (int i = tid + 4096; i < 4160; i += NT) bufA[i] = p.b2a[i - 4096];
    __syncthreads();

    // ---- node = node0 @ W1a + b1a (write transposed into sNT) ----
    {
        const int n = tid >> 3, f0 = (tid & 7) << 2;
        float a0 = p.b1a[f0], a1 = p.b1a[f0+1], a2 = p.b1a[f0+2], a3 = p.b1a[f0+3];
        const float* r = sBase + n*32;
        #pragma unroll 8
        for (int k = 0; k < 32; ++k) {
            float a = r[k];
            float4 w = *(const float4*)(p.W1a + k*32 + f0);
            a0 += a*w.x; a1 += a*w.y; a2 += a*w.z; a3 += a*w.w;
        }
        sNT[(f0+0)*33 + n] = a0; sNT[(f0+1)*33 + n] = a1;
        sNT[(f0+2)*33 + n] = a2; sNT[(f0+3)*33 + n] = a3;
    }
    __syncthreads();

    const int iters = p.iterp ? *p.iterp : 3;

    for (int it = 0; it < iters; ++it) {
        // ---- base = node@W2a[0:32]+b2a ; proj = node@W2a[32:64] ----
        {
            const int n = tid >> 3, c0 = (tid & 7) << 3;
            ull bacc[4], pacc[4];
            {
                ulonglong2 b0 = *(const ulonglong2*)(bufA + 4096 + c0);
                ulonglong2 b1 = *(const ulonglong2*)(bufA + 4096 + c0 + 4);
                bacc[0]=b0.x; bacc[1]=b0.y; bacc[2]=b1.x; bacc[3]=b1.y;
            }
            const ull z = dup2(0.0f);
            #pragma unroll
            for (int o = 0; o < 4; ++o) pacc[o] = z;
            #pragma unroll 4
            for (int k = 0; k < 32; ++k) {
                ull aa = dup2(sNT[k*33 + n]);
                ulonglong2 wb0 = *(const ulonglong2*)(bufA + k*64 + c0);
                ulonglong2 wb1 = *(const ulonglong2*)(bufA + k*64 + c0 + 4);
                ulonglong2 wp0 = *(const ulonglong2*)(bufA + (32+k)*64 + c0);
                ulonglong2 wp1 = *(const ulonglong2*)(bufA + (32+k)*64 + c0 + 4);
                bacc[0] = fma2(aa, wb0.x, bacc[0]); bacc[1] = fma2(aa, wb0.y, bacc[1]);
                bacc[2] = fma2(aa, wb1.x, bacc[2]); bacc[3] = fma2(aa, wb1.y, bacc[3]);
                pacc[0] = fma2(aa, wp0.x, pacc[0]); pacc[1] = fma2(aa, wp0.y, pacc[1]);
                pacc[2] = fma2(aa, wp1.x, pacc[2]); pacc[3] = fma2(aa, wp1.y, pacc[3]);
            }
            *(ulonglong2*)(sBase + n*68 + c0)     = make_ulonglong2(bacc[0], bacc[1]);
            *(ulonglong2*)(sBase + n*68 + c0 + 4) = make_ulonglong2(bacc[2], bacc[3]);
            *(ulonglong2*)(sProj + n*68 + c0)     = make_ulonglong2(pacc[0], pacc[1]);
            *(ulonglong2*)(sProj + n*68 + c0 + 4) = make_ulonglong2(pacc[2], pacc[3]);
        }
        __syncthreads();

        // ---- edge phase: 2 passes; f32x2 lanes = (edge of node iA, edge of node iB).
        //      ONE acc bank for both edges; weight sweeps amortized over 2 edges. ----
        for (int pass = 0; pass < 2; ++pass) {
            const int iA = pass * 16 + warp;
            const int iB = iA + 8;
            const int q  = (lane < 31) ? lane : 30;
            const int jA = q + (q >= iA);
            const int jB = q + (q >= iB);
            float eA0, eA1, eB0, eB1;
            unpack2(*(const ull*)(sEdge + (iA*31 + q)*2), eA0, eA1);
            unpack2(*(const ull*)(sEdge + (iB*31 + q)*2), eB0, eB1);
            const ull ep0 = pack2(eA0, eB0), ep1 = pack2(eA1, eB1);
            const float* bA = sBase + iA*68;
            const float* bBr = sBase + iB*68;
            const float* pA = sProj + jA*68;
            const float* pB = sProj + jB*68;

            ull acc[32];
            #pragma unroll
            for (int c = 0; c < 32; ++c) acc[c] = dup2(bBs[c]);

            #pragma unroll 2
            for (int t = 0; t < 16; ++t) {        // quads of layer-1 output cols
                float4 bA4 = *(const float4*)(bA  + 4*t);
                float4 bB4 = *(const float4*)(bBr + 4*t);
                float4 pA4 = *(const float4*)(pA  + 4*t);
                float4 pB4 = *(const float4*)(pB  + 4*t);
                float4 w64q = *(const float4*)(w45x + 4*t);
                float4 w65q = *(const float4*)(w45x + 64 + 4*t);
                ull u0 = fma2(ep1, dup2(w65q.x),
                         fma2(ep0, dup2(w64q.x),
                         add2(pack2(bA4.x, bB4.x), pack2(pA4.x, pB4.x))));
                ull u1 = fma2(ep1, dup2(w65q.y),
                         fma2(ep0, dup2(w64q.y),
                         add2(pack2(bA4.y, bB4.y), pack2(pA4.y, pB4.y))));
                ull u2 = fma2(ep1, dup2(w65q.z),
                         fma2(ep0, dup2(w64q.z),
                         add2(pack2(bA4.z, bB4.z), pack2(pA4.z, pB4.z))));
                ull u3 = fma2(ep1, dup2(w65q.w),
                         fma2(ep0, dup2(w64q.w),
                         add2(pack2(bA4.w, bB4.w), pack2(pA4.w, pB4.w))));
                ull g0 = gelu2(u0), g1 = gelu2(u1), g2 = gelu2(u2), g3 = gelu2(u3);
                const int k0 = 4*t;
                #pragma unroll
                for (int cq = 0; cq < 8; ++cq) {
                    float4 wr0 = *(const float4*)(W2bs + (k0+0)*32 + 4*cq);
                    float4 wr1 = *(const float4*)(W2bs + (k0+1)*32 + 4*cq);
                    float4 wr2 = *(const float4*)(W2bs + (k0+2)*32 + 4*cq);
                    float4 wr3 = *(const float4*)(W2bs + (k0+3)*32 + 4*cq);
                    acc[4*cq+0] = fma2(g0, dup2(wr0.x), acc[4*cq+0]);
                    acc[4*cq+1] = fma2(g0, dup2(wr0.y), acc[4*cq+1]);
                    acc[4*cq+2] = fma2(g0, dup2(wr0.z), acc[4*cq+2]);
                    acc[4*cq+3] = fma2(g0, dup2(wr0.w), acc[4*cq+3]);
                    acc[4*cq+0] = fma2(g1, dup2(wr1.x), acc[4*cq+0]);
                    acc[4*cq+1] = fma2(g1, dup2(wr1.y), acc[4*cq+1]);
                    acc[4*cq+2] = fma2(g1, dup2(wr1.z), acc[4*cq+2]);
                    acc[4*cq+3] = fma2(g1, dup2(wr1.w), acc[4*cq+3]);
                    acc[4*cq+0] = fma2(g2, dup2(wr2.x), acc[4*cq+0]);
                    acc[4*cq+1] = fma2(g2, dup2(wr2.y), acc[4*cq+1]);
                    acc[4*cq+2] = fma2(g2, dup2(wr2.z), acc[4*cq+2]);
                    acc[4*cq+3] = fma2(g2, dup2(wr2.w), acc[4*cq+3]);
                    acc[4*cq+0] = fma2(g3, dup2(wr3.x), acc[4*cq+0]);
                    acc[4*cq+1] = fma2(g3, dup2(wr3.y), acc[4*cq+1]);
                    acc[4*cq+2] = fma2(g3, dup2(wr3.z), acc[4*cq+2]);
                    acc[4*cq+3] = fma2(g3, dup2(wr3.w), acc[4*cq+3]);
                }
            }

            // gelu m2 in place (packed pair = both edges)
            #pragma unroll
            for (int c = 0; c < 32; ++c) acc[c] = gelu2(acc[c]);

            const ull mask2 = dup2((lane < 31) ? 1.0f : 0.0f);

            // layer 3 in quarters of 8 output cols (macc = 8 ull = 16 regs)
            #pragma unroll
            for (int qt = 0; qt < 4; ++qt) {
                ull macc[8];
                #pragma unroll
                for (int s = 0; s < 8; ++s) {
                    const int c = qt*8 + s;
                    ull a = dup2(bCs[c]);
                    const float* wr = wCtr + c*32;
                    #pragma unroll
                    for (int kq = 0; kq < 8; ++kq) {
                        float4 w = *(const float4*)(wr + 4*kq);
                        a = fma2(acc[4*kq+0], dup2(w.x), a);
                        a = fma2(acc[4*kq+1], dup2(w.y), a);
                        a = fma2(acc[4*kq+2], dup2(w.z), a);
                        a = fma2(acc[4*kq+3], dup2(w.w), a);
                    }
                    macc[s] = mul2(gelu2(a), mask2);
                }
                // transpose-reduce 8 slots over 32 lanes
                #pragma unroll
                for (int s = 0; s < 3; ++s) {
                    const int off = 1 << s;
                    const int h = 4 >> s;
                    const bool keep_low = ((lane >> s) & 1) == 0;
                    #pragma unroll
                    for (int r = 0; r < 4; ++r) {
                        if (r < h) {
                            ull send = keep_low ? macc[r + h] : macc[r];
                            ull recv = shflxor64(send, off);
                            ull mine = keep_low ? macc[r] : macc[r + h];
                            macc[r] = add2(mine, recv);
                        }
                    }
                }
                macc[0] = add2(macc[0], shflxor64(macc[0], 8));
                macc[0] = add2(macc[0], shflxor64(macc[0], 16));
                if (lane < 8) {
                    const int e = qt*8 + (((lane & 1) << 2) |
                                          (((lane >> 1) & 1) << 1) |
                                          ((lane >> 2) & 1));
                    float vA, vB; unpack2(macc[0], vA, vB);
                    sMi[iA*36 + e] = vA;
                    sMi[iB*36 + e] = vB;
                }
            }
        }
        __syncthreads();

        // ---- GRU cell (GELU new gate), packed col-pairs ----
        {
            const int n  = tid >> 3;
            const int c0 = (tid & 7) << 3;
            ull ar[4], az[4], an_[4], hn_[4];
            #pragma unroll
            for (int o = 0; o < 4; ++o) {
                ull bi_r = *(const ull*)(p.bih + c0 + 2*o);
                ull bh_r = *(const ull*)(p.bhh + c0 + 2*o);
                ull bi_z = *(const ull*)(p.bih + 64 + c0 + 2*o);
                ull bh_z = *(const ull*)(p.bhh + 64 + c0 + 2*o);
                ar[o]  = add2(bi_r, bh_r);
                az[o]  = add2(bi_z, bh_z);
                an_[o] = *(const ull*)(p.bih + 128 + c0 + 2*o);
                hn_[o] = *(const ull*)(p.bhh + 128 + c0 + 2*o);
            }
            const float* mi = sMi + n*36;
            #pragma unroll 2
            for (int k = 0; k < 34; ++k) {
                ull aa = dup2(mi[k]);
                const float* w = p.Wih + k*192;
                ulonglong2 r01 = *(const ulonglong2*)(w + c0);
                ulonglong2 r23 = *(const ulonglong2*)(w + c0 + 4);
                ulonglong2 z01 = *(const ulonglong2*)(w + 64 + c0);
                ulonglong2 z23 = *(const ulonglong2*)(w + 64 + c0 + 4);
                ulonglong2 n01 = *(const ulonglong2*)(w + 128 + c0);
                ulonglong2 n23 = *(const ulonglong2*)(w + 128 + c0 + 4);
                ar[0]=fma2(aa,r01.x,ar[0]); ar[1]=fma2(aa,r01.y,ar[1]);
                ar[2]=fma2(aa,r23.x,ar[2]); ar[3]=fma2(aa,r23.y,ar[3]);
                az[0]=fma2(aa,z01.x,az[0]); az[1]=fma2(aa,z01.y,az[1]);
                az[2]=fma2(aa,z23.x,az[2]); az[3]=fma2(aa,z23.y,az[3]);
                an_[0]=fma2(aa,n01.x,an_[0]); an_[1]=fma2(aa,n01.y,an_[1]);
                an_[2]=fma2(aa,n23.x,an_[2]); an_[3]=fma2(aa,n23.y,an_[3]);
            }
            const float* hv = sH + n*65;
            #pragma unroll 2
            for (int k = 0; k < 64; ++k) {
                ull aa = dup2(hv[k]);
                const float* w = p.Whh + k*192;
                ulonglong2 r01 = *(const ulonglong2*)(w + c0);
                ulonglong2 r23 = *(const ulonglong2*)(w + c0 + 4);
                ulonglong2 z01 = *(const ulonglong2*)(w + 64 + c0);
                ulonglong2 z23 = *(const ulonglong2*)(w + 64 + c0 + 4);
                ulonglong2 n01 = *(const ulonglong2*)(w + 128 + c0);
                ulonglong2 n23 = *(const ulonglong2*)(w + 128 + c0 + 4);
                ar[0]=fma2(aa,r01.x,ar[0]); ar[1]=fma2(aa,r01.y,ar[1]);
                ar[2]=fma2(aa,r23.x,ar[2]); ar[3]=fma2(aa,r23.y,ar[3]);
                az[0]=fma2(aa,z01.x,az[0]); az[1]=fma2(aa,z01.y,az[1]);
                az[2]=fma2(aa,z23.x,az[2]); az[3]=fma2(aa,z23.y,az[3]);
                hn_[0]=fma2(aa,n01.x,hn_[0]); hn_[1]=fma2(aa,n01.y,hn_[1]);
                hn_[2]=fma2(aa,n23.x,hn_[2]); hn_[3]=fma2(aa,n23.y,hn_[3]);
            }
            float hnew[8];
            #pragma unroll
            for (int o = 0; o < 4; ++o) {
                float r0, r1, z0, z1, in0, in1, hn0, hn1;
                unpack2(ar[o], r0, r1);
                unpack2(az[o], z0, z1);
                unpack2(an_[o], in0, in1);
                unpack2(hn_[o], hn0, hn1);
                float rr0 = sigm_f(r0), rr1 = sigm_f(r1);
                float zz0 = sigm_f(z0), zz1 = sigm_f(z1);
                float g0, g1;
                unpack2(gelu2(pack2(fmaf(rr0, hn0, in0), fmaf(rr1, hn1, in1))), g0, g1);
                hnew[2*o]   = (1.0f - zz0) * g0 + zz0 * hv[c0 + 2*o];
                hnew[2*o+1] = (1.0f - zz1) * g1 + zz1 * hv[c0 + 2*o + 1];
            }
            __syncthreads();
            #pragma unroll
            for (int o = 0; o < 8; ++o) sH[n*65 + c0 + o] = hnew[o];
        }
        __syncthreads();

        // ---- node = h @ W3b + b3b  (packed, write transposed into sNT) ----
        {
            const int n = tid >> 3, f0 = (tid & 7) << 2;
            ull a01 = *(const ull*)(p.b3b + f0);
            ull a23 = *(const ull*)(p.b3b + f0 + 2);
            const float* hv = sH + n*65;
            #pragma unroll 4
            for (int k = 0; k < 64; ++k) {
                ull aa = dup2(hv[k]);
                ulonglong2 w2 = *(const ulonglong2*)(p.W3b + k*32 + f0);
                a01 = fma2(aa, w2.x, a01);
                a23 = fma2(aa, w2.y, a23);
            }
            float v0, v1, v2, v3;
            unpack2(a01, v0, v1); unpack2(a23, v2, v3);
            sNT[(f0+0)*33 + n] = v0; sNT[(f0+1)*33 + n] = v1;
            sNT[(f0+2)*33 + n] = v2; sNT[(f0+3)*33 + n] = v3;
        }
        __syncthreads();
    }

    // ---- readout (scratch: bufA=t1, sBase=t2, sProj=t3, sBase=t4) ----
    {   // t1 = node @ W4a + b4a : [32][68]
        const int n = tid >> 3, f0 = (tid & 7) << 3;
        ull acc[4];
        acc[0] = *(const ull*)(p.b4a + f0);
        acc[1] = *(const ull*)(p.b4a + f0 + 2);
        acc[2] = *(const ull*)(p.b4a + f0 + 4);
        acc[3] = *(const ull*)(p.b4a + f0 + 6);
        #pragma unroll 4
        for (int k = 0; k < 32; ++k) {
            ull aa = dup2(sNT[k*33 + n]);
            ulonglong2 w0 = *(const ulonglong2*)(p.W4a + k*64 + f0);
            ulonglong2 w1 = *(const ulonglong2*)(p.W4a + k*64 + f0 + 4);
            acc[0] = fma2(aa, w0.x, acc[0]); acc[1] = fma2(aa, w0.y, acc[1]);
            acc[2] = fma2(aa, w1.x, acc[2]); acc[3] = fma2(aa, w1.y, acc[3]);
        }
        *(ulonglong2*)(bufA + n*68 + f0)     = make_ulonglong2(acc[0], acc[1]);
        *(ulonglong2*)(bufA + n*68 + f0 + 4) = make_ulonglong2(acc[2], acc[3]);
    }
    __syncthreads();
    {   // t2 = t1 @ W4b + b4b : [32][36] into sBase
        const int n = tid >> 3, f0 = (tid & 7) << 2;
        ull a01 = *(const ull*)(p.b4b + f0);
        ull a23 = *(const ull*)(p.b4b + f0 + 2);
        const float* r = bufA + n*68;
        #pragma unroll 4
        for (int k = 0; k < 64; ++k) {
            ull aa = dup2(r[k]);
            ulonglong2 w2 = *(const ulonglong2*)(p.W4b + k*32 + f0);
            a01 = fma2(aa, w2.x, a01);
            a23 = fma2(aa, w2.y, a23);
        }
        *(ull*)(sBase + n*36 + f0)     = a01;
        *(ull*)(sBase + n*36 + f0 + 2) = a23;
    }
    __syncthreads();
    {   // t3 = t2 @ W4c + b4c : [32][36] into sProj
        const int n = tid >> 3, f0 = (tid & 7) << 2;
        ull a01 = *(const ull*)(p.b4c + f0);
        ull a23 = *(const ull*)(p.b4c + f0 + 2);
        const float* r = sBase + n*36;
        #pragma unroll 4
        for (int k = 0; k < 32; ++k) {
            ull aa = dup2(r[k]);
            ulonglong2 w2 = *(const ulonglong2*)(p.W4c + k*32 + f0);
            a01 = fma2(aa, w2.x, a01);
            a23 = fma2(aa, w2.y, a23);
        }
        *(ull*)(sProj + n*36 + f0)     = a01;
        *(ull*)(sProj + n*36 + f0 + 2) = a23;
    }
    __syncthreads();
    {   // t4 = t3 @ W5a + b5a : [32][18] into sBase
        const int n = tid >> 3, f0 = (tid & 7) << 1;
        float a0 = p.b5a[f0], a1 = p.b5a[f0 + 1];
        const float* r = sProj + n*36;
        #pragma unroll 8
        for (int k = 0; k < 32; ++k) {
            float a = r[k];
            a0 += a * p.W5a[k*16 + f0];
            a1 += a * p.W5a[k*16 + f0 + 1];
        }
        sBase[n*18 + f0]     = a0;
        sBase[n*18 + f0 + 1] = a1;
    }
    __syncthreads();
    if (tid < 64) {
        const int n = tid >> 1, col = tid & 1;
        float acc = p.b5b[col];
        const float* r = sBase + n*18;
        #pragma unroll
        for (int k = 0; k < 16; ++k) acc += r[k] * p.W5b[k*2 + col];
        if (col == 0) p.out[b*32 + n] = acc;
        else          p.out[32768 + b*32 + n] = 1.0f / acc;
    }
}

extern "C" void kernel_launch(void* const* d_in, const int* in_sizes, int n_in,
                              void* d_out, int out_size) {
    const int has_iter = (n_in >= 32) ? 1 : 0;
    const int base = has_iter ? 8 : 7;

    GnnParams p;
    p.node0 = (const float*)d_in[0];
    p.edge  = (const float*)d_in[1];
    p.h0    = (const float*)d_in[2];
    p.mean  = (const float*)d_in[3];
    p.vari  = (const float*)d_in[4];
    p.iterp = has_iter ? (const int*)d_in[7] : nullptr;
    p.W1a = (const float*)d_in[base+0];  p.b1a = (const float*)d_in[base+1];
    p.W2a = (const float*)d_in[base+2];  p.b2a = (const float*)d_in[base+3];
    p.W2b = (const float*)d_in[base+4];  p.b2b = (const float*)d_in[base+5];
    p.W2c = (const float*)d_in[base+6];  p.b2c = (const float*)d_in[base+7];
    p.Wih = (const float*)d_in[base+8];  p.Whh = (const float*)d_in[base+9];
    p.bih = (const float*)d_in[base+10]; p.bhh = (const float*)d_in[base+11];
    p.W3b = (const float*)d_in[base+12]; p.b3b = (const float*)d_in[base+13];
    p.W4a = (const float*)d_in[base+14]; p.b4a = (const float*)d_in[base+15];
    p.W4b = (const float*)d_in[base+16]; p.b4b = (const float*)d_in[base+17];
    p.W4c = (const float*)d_in[base+18]; p.b4c = (const float*)d_in[base+19];
    p.W5a = (const float*)d_in[base+20]; p.b5a = (const float*)d_in[base+21];
    p.W5b = (const float*)d_in[base+22]; p.b5b = (const float*)d_in[base+23];
    p.out = (float*)d_out;

    cudaFuncSetAttribute(gnn_kernel,
                         cudaFuncAttributeMaxDynamicSharedMemorySize,
                         SMEM_FLOATS * (int)sizeof(float));
    gnn_kernel<<<1024, NT, SMEM_FLOATS * sizeof(float)>>>(p);
}

// round 15
// speedup vs baseline: 4.1757x; 1.0068x over previous
#include <cuda_runtime.h>
#include <math.h>

#define NT 256
typedef unsigned long long ull;

// Shared layout (float offsets)
#define OFF_NT    0        // nodeT [32 feat][32 node] stride 33 = 1056
#define OFF_H     1056     // [32][65] = 2080
#define OFF_MI    3136     // [32][36] = 1152
#define OFF_EDGE  4288     // [992][2] = 1984
#define OFF_BASE  6272     // [32][68] = 2176 (stride 68 -> 16B aligned rows)
#define OFF_PROJ  8448     // [32][68] = 2176
#define OFF_A     10624    // staging W2a[0:64]+b2a (4160) / readout t1 (2176)
#define OFF_W2B   14784    // W2b plain [64][32]: 2048 floats
#define OFF_WCTR  16832    // W2c transposed [c][k]: 1024 floats
#define OFF_W45   17856    // W2a row64 (64) then row65 (64): 128 floats
#define OFF_B2B   17984    // 32
#define OFF_B2C   18016    // 32
#define SMEM_FLOATS 18048  // 72,192 B -> 2 CTAs/SM

__device__ __forceinline__ float rcp_fast(float x) {
    float r; asm("rcp.approx.f32 %0, %1;" : "=f"(r) : "f"(x)); return r;
}
__device__ __forceinline__ float ex2_fast(float x) {
    float r; asm("ex2.approx.f32 %0, %1;" : "=f"(r) : "f"(x)); return r;
}
__device__ __forceinline__ ull pack2(float lo, float hi) {
    ull r; asm("mov.b64 %0, {%1, %2};" : "=l"(r) : "f"(lo), "f"(hi)); return r;
}
__device__ __forceinline__ ull dup2(float x) { return pack2(x, x); }
__device__ __forceinline__ void unpack2(ull v, float& lo, float& hi) {
    asm("mov.b64 {%0, %1}, %2;" : "=f"(lo), "=f"(hi) : "l"(v));
}
__device__ __forceinline__ ull fma2(ull a, ull b, ull c) {
    ull d; asm("fma.rn.f32x2 %0, %1, %2, %3;" : "=l"(d) : "l"(a), "l"(b), "l"(c));
    return d;
}
__device__ __forceinline__ ull add2(ull a, ull b) {
    ull d; asm("add.rn.f32x2 %0, %1, %2;" : "=l"(d) : "l"(a), "l"(b));
    return d;
}
__device__ __forceinline__ ull mul2(ull a, ull b) {
    ull d; asm("mul.rn.f32x2 %0, %1, %2;" : "=l"(d) : "l"(a), "l"(b));
    return d;
}
__device__ __forceinline__ ull shflxor64(ull v, int m) {
    unsigned lo = (unsigned)v, hi = (unsigned)(v >> 32);
    lo = __shfl_xor_sync(0xffffffffu, lo, m);
    hi = __shfl_xor_sync(0xffffffffu, hi, m);
    return ((ull)hi << 32) | lo;
}

// Packed GELU on an f32x2 pair: A&S 7.1.26 erf; poly on FMA pipe, 2 RCP + 2 EX2 on MUFU.
__device__ __forceinline__ ull gelu2(ull x2) {
    ull s2 = mul2(x2, dup2(0.7071067811865476f));
    ull a2 = s2 & 0x7FFFFFFF7FFFFFFFULL;
    ull v2 = fma2(a2, dup2(0.3275911f), dup2(1.0f));
    float v0, v1; unpack2(v2, v0, v1);
    ull r2 = pack2(rcp_fast(v0), rcp_fast(v1));
    ull u2 = mul2(a2, a2);
    ull y2 = mul2(u2, dup2(-1.4426950408889634f));
    float y0, y1; unpack2(y2, y0, y1);
    ull e2 = pack2(ex2_fast(y0), ex2_fast(y1));
    ull q2 = dup2(1.061405429f);
    q2 = fma2(q2, r2, dup2(-1.453152027f));
    q2 = fma2(q2, r2, dup2(1.421413741f));
    q2 = fma2(q2, r2, dup2(-0.284496736f));
    q2 = fma2(q2, r2, dup2(0.254829592f));
    q2 = mul2(q2, r2);
    ull t2 = mul2(q2, e2);
    ull E2 = fma2(t2, dup2(-1.0f), dup2(1.0f));
    E2 = E2 | (s2 & 0x8000000080000000ULL);
    ull hx = mul2(x2, dup2(0.5f));
    return fma2(hx, E2, hx);
}
__device__ __forceinline__ float sigm_f(float x) {
    return rcp_fast(1.0f + ex2_fast(-x * 1.4426950408889634f));
}

struct GnnParams {
    const float *node0, *edge, *h0, *mean, *vari;
    const int   *iterp;
    const float *W1a, *b1a, *W2a, *b2a, *W2b, *b2b, *W2c, *b2c;
    const float *Wih, *Whh, *bih, *bhh, *W3b, *b3b;
    const float *W4a, *b4a, *W4b, *b4b, *W4c, *b4c, *W5a, *b5a, *W5b, *b5b;
    float *out;
};

__global__ __launch_bounds__(NT, 2)
void gnn_kernel(GnnParams p) {
    extern __shared__ float sm[];
    const int tid  = threadIdx.x;
    const int b    = blockIdx.x;
    const int warp = tid >> 5, lane = tid & 31;

    float* sNT   = sm + OFF_NT;
    float* sH    = sm + OFF_H;     // stride 65
    float* sMi   = sm + OFF_MI;    // stride 36
    float* sEdge = sm + OFF_EDGE;
    float* sBase = sm + OFF_BASE;  // stride 68
    float* sProj = sm + OFF_PROJ;  // stride 68
    float* bufA  = sm + OFF_A;
    const float* W2bs = sm + OFF_W2B;
    const float* wCtr = sm + OFF_WCTR;
    const float* w45x = sm + OFF_W45;
    const float* bBs  = sm + OFF_B2B;
    const float* bCs  = sm + OFF_B2C;

    // ---- init copies (once) ----
    for (int i = tid; i < 992*2; i += NT) sEdge[i] = p.edge[b*1984 + i];
    for (int i = tid; i < 32*64; i += NT) {
        int n = i >> 6, k = i & 63;
        sH[n*65 + k] = p.h0[b*2048 + i];
    }
    for (int i = tid; i < 2048;  i += NT) sm[OFF_W2B + i] = p.W2b[i];
    for (int i = tid; i < 1024;  i += NT) {    // wCtr[c][k] = W2c[k][c]
        int c = i >> 5, k = i & 31;
        sm[OFF_WCTR + i] = p.W2c[k*32 + c];
    }
    for (int i = tid; i < 128;   i += NT) sm[OFF_W45 + i] = p.W2a[64*64 + i];
    for (int i = tid; i < 32;    i += NT) {
        sm[OFF_B2B + i] = p.b2b[i];
        sm[OFF_B2C + i] = p.b2c[i];
    }
    if (tid < 32) {
        sMi[tid*36 + 32] = p.mean[b*32 + tid];
        sMi[tid*36 + 33] = 1.0f / p.vari[b*32 + tid];
    }
    for (int i = tid; i < 1024; i += NT) sBase[i] = p.node0[b*1024 + i];
    for (int i = tid; i < 4096; i += NT) bufA[i] = p.W2a[i];
    for (int i = tid + 4096; i < 4160; i += NT) bufA[i] = p.b2a[i - 4096];
    __syncthreads();

    // ---- node = node0 @ W1a + b1a (write transposed into sNT) ----
    {
        const int n = tid >> 3, f0 = (tid & 7) << 2;
        float a0 = p.b1a[f0], a1 = p.b1a[f0+1], a2 = p.b1a[f0+2], a3 = p.b1a[f0+3];
        const float* r = sBase + n*32;
        #pragma unroll 8
        for (int k = 0; k < 32; ++k) {
            float a = r[k];
            float4 w = *(const float4*)(p.W1a + k*32 + f0);
            a0 += a*w.x; a1 += a*w.y; a2 += a*w.z; a3 += a*w.w;
        }
        sNT[(f0+0)*33 + n] = a0; sNT[(f0+1)*33 + n] = a1;
        sNT[(f0+2)*33 + n] = a2; sNT[(f0+3)*33 + n] = a3;
    }
    __syncthreads();

    const int iters = p.iterp ? *p.iterp : 3;

    for (int it = 0; it < iters; ++it) {
        // ---- base = node@W2a[0:32]+b2a ; proj = node@W2a[32:64] ----
        {
            const int n = tid >> 3, c0 = (tid & 7) << 3;
            ull bacc[4], pacc[4];
            {
                ulonglong2 b0 = *(const ulonglong2*)(bufA + 4096 + c0);
                ulonglong2 b1 = *(const ulonglong2*)(bufA + 4096 + c0 + 4);
                bacc[0]=b0.x; bacc[1]=b0.y; bacc[2]=b1.x; bacc[3]=b1.y;
            }
            const ull z = dup2(0.0f);
            #pragma unroll
            for (int o = 0; o < 4; ++o) pacc[o] = z;
            #pragma unroll 4
            for (int k = 0; k < 32; ++k) {
                ull aa = dup2(sNT[k*33 + n]);
                ulonglong2 wb0 = *(const ulonglong2*)(bufA + k*64 + c0);
                ulonglong2 wb1 = *(const ulonglong2*)(bufA + k*64 + c0 + 4);
                ulonglong2 wp0 = *(const ulonglong2*)(bufA + (32+k)*64 + c0);
                ulonglong2 wp1 = *(const ulonglong2*)(bufA + (32+k)*64 + c0 + 4);
                bacc[0] = fma2(aa, wb0.x, bacc[0]); bacc[1] = fma2(aa, wb0.y, bacc[1]);
                bacc[2] = fma2(aa, wb1.x, bacc[2]); bacc[3] = fma2(aa, wb1.y, bacc[3]);
                pacc[0] = fma2(aa, wp0.x, pacc[0]); pacc[1] = fma2(aa, wp0.y, pacc[1]);
                pacc[2] = fma2(aa, wp1.x, pacc[2]); pacc[3] = fma2(aa, wp1.y, pacc[3]);
            }
            *(ulonglong2*)(sBase + n*68 + c0)     = make_ulonglong2(bacc[0], bacc[1]);
            *(ulonglong2*)(sBase + n*68 + c0 + 4) = make_ulonglong2(bacc[2], bacc[3]);
            *(ulonglong2*)(sProj + n*68 + c0)     = make_ulonglong2(pacc[0], pacc[1]);
            *(ulonglong2*)(sProj + n*68 + c0 + 4) = make_ulonglong2(pacc[2], pacc[3]);
        }
        __syncthreads();

        // ---- edge phase: 2 passes; f32x2 lanes = (edge of node iA, edge of node iB) ----
        for (int pass = 0; pass < 2; ++pass) {
            const int iA = pass * 16 + warp;
            const int iB = iA + 8;
            const int q  = (lane < 31) ? lane : 30;
            const int jA = q + (q >= iA);
            const int jB = q + (q >= iB);
            float eA0, eA1, eB0, eB1;
            unpack2(*(const ull*)(sEdge + (iA*31 + q)*2), eA0, eA1);
            unpack2(*(const ull*)(sEdge + (iB*31 + q)*2), eB0, eB1);
            const ull ep0 = pack2(eA0, eB0), ep1 = pack2(eA1, eB1);
            const float* bA = sBase + iA*68;
            const float* bBr = sBase + iB*68;
            const float* pA = sProj + jA*68;
            const float* pB = sProj + jB*68;

            ull acc[32];
            #pragma unroll
            for (int c = 0; c < 32; ++c) acc[c] = dup2(bBs[c]);

            #pragma unroll 4
            for (int t = 0; t < 16; ++t) {        // quads of layer-1 output cols
                float4 bA4 = *(const float4*)(bA  + 4*t);
                float4 bB4 = *(const float4*)(bBr + 4*t);
                float4 pA4 = *(const float4*)(pA  + 4*t);
                float4 pB4 = *(const float4*)(pB  + 4*t);
                float4 w64q = *(const float4*)(w45x + 4*t);
                float4 w65q = *(const float4*)(w45x + 64 + 4*t);
                ull u0 = fma2(ep1, dup2(w65q.x),
                         fma2(ep0, dup2(w64q.x),
                         add2(pack2(bA4.x, bB4.x), pack2(pA4.x, pB4.x))));
                ull u1 = fma2(ep1, dup2(w65q.y),
                         fma2(ep0, dup2(w64q.y),
                         add2(pack2(bA4.y, bB4.y), pack2(pA4.y, pB4.y))));
                ull u2 = fma2(ep1, dup2(w65q.z),
                         fma2(ep0, dup2(w64q.z),
                         add2(pack2(bA4.z, bB4.z), pack2(pA4.z, pB4.z))));
                ull u3 = fma2(ep1, dup2(w65q.w),
                         fma2(ep0, dup2(w64q.w),
                         add2(pack2(bA4.w, bB4.w), pack2(pA4.w, pB4.w))));
                ull g0 = gelu2(u0), g1 = gelu2(u1), g2 = gelu2(u2), g3 = gelu2(u3);
                const int k0 = 4*t;
                #pragma unroll
                for (int cq = 0; cq < 8; ++cq) {
                    float4 wr0 = *(const float4*)(W2bs + (k0+0)*32 + 4*cq);
                    float4 wr1 = *(const float4*)(W2bs + (k0+1)*32 + 4*cq);
                    float4 wr2 = *(const float4*)(W2bs + (k0+2)*32 + 4*cq);
                    float4 wr3 = *(const float4*)(W2bs + (k0+3)*32 + 4*cq);
                    acc[4*cq+0] = fma2(g0, dup2(wr0.x), acc[4*cq+0]);
                    acc[4*cq+1] = fma2(g0, dup2(wr0.y), acc[4*cq+1]);
                    acc[4*cq+2] = fma2(g0, dup2(wr0.z), acc[4*cq+2]);
                    acc[4*cq+3] = fma2(g0, dup2(wr0.w), acc[4*cq+3]);
                    acc[4*cq+0] = fma2(g1, dup2(wr1.x), acc[4*cq+0]);
                    acc[4*cq+1] = fma2(g1, dup2(wr1.y), acc[4*cq+1]);
                    acc[4*cq+2] = fma2(g1, dup2(wr1.z), acc[4*cq+2]);
                    acc[4*cq+3] = fma2(g1, dup2(wr1.w), acc[4*cq+3]);
                    acc[4*cq+0] = fma2(g2, dup2(wr2.x), acc[4*cq+0]);
                    acc[4*cq+1] = fma2(g2, dup2(wr2.y), acc[4*cq+1]);
                    acc[4*cq+2] = fma2(g2, dup2(wr2.z), acc[4*cq+2]);
                    acc[4*cq+3] = fma2(g2, dup2(wr2.w), acc[4*cq+3]);
                    acc[4*cq+0] = fma2(g3, dup2(wr3.x), acc[4*cq+0]);
                    acc[4*cq+1] = fma2(g3, dup2(wr3.y), acc[4*cq+1]);
                    acc[4*cq+2] = fma2(g3, dup2(wr3.z), acc[4*cq+2]);
                    acc[4*cq+3] = fma2(g3, dup2(wr3.w), acc[4*cq+3]);
                }
            }

            // gelu m2 in place (packed pair = both edges)
            #pragma unroll
            for (int c = 0; c < 32; ++c) acc[c] = gelu2(acc[c]);

            const ull mask2 = dup2((lane < 31) ? 1.0f : 0.0f);

            // layer 3 in quarters of 8 output cols; per-col chain split in two
            #pragma unroll
            for (int qt = 0; qt < 4; ++qt) {
                ull macc[8];
                #pragma unroll
                for (int s = 0; s < 8; ++s) {
                    const int c = qt*8 + s;
                    ull a  = dup2(bCs[c]);
                    ull a2 = dup2(0.0f);
                    const float* wr = wCtr + c*32;
                    #pragma unroll
                    for (int kq = 0; kq < 4; ++kq) {
                        float4 w0 = *(const float4*)(wr + 4*kq);
                        float4 w1 = *(const float4*)(wr + 16 + 4*kq);
                        a  = fma2(acc[4*kq+0],  dup2(w0.x), a);
                        a2 = fma2(acc[16+4*kq], dup2(w1.x), a2);
                        a  = fma2(acc[4*kq+1],  dup2(w0.y), a);
                        a2 = fma2(acc[16+4*kq+1], dup2(w1.y), a2);
                        a  = fma2(acc[4*kq+2],  dup2(w0.z), a);
                        a2 = fma2(acc[16+4*kq+2], dup2(w1.z), a2);
                        a  = fma2(acc[4*kq+3],  dup2(w0.w), a);
                        a2 = fma2(acc[16+4*kq+3], dup2(w1.w), a2);
                    }
                    macc[s] = mul2(gelu2(add2(a, a2)), mask2);
                }
                // transpose-reduce 8 slots over 32 lanes
                #pragma unroll
                for (int s = 0; s < 3; ++s) {
                    const int off = 1 << s;
                    const int h = 4 >> s;
                    const bool keep_low = ((lane >> s) & 1) == 0;
                    #pragma unroll
                    for (int r = 0; r < 4; ++r) {
                        if (r < h) {
                            ull send = keep_low ? macc[r + h] : macc[r];
                            ull recv = shflxor64(send, off);
                            ull mine = keep_low ? macc[r] : macc[r + h];
                            macc[r] = add2(mine, recv);
                        }
                    }
                }
                macc[0] = add2(macc[0], shflxor64(macc[0], 8));
                macc[0] = add2(macc[0], shflxor64(macc[0], 16));
                if (lane < 8) {
                    const int e = qt*8 + (((lane & 1) << 2) |
                                          (((lane >> 1) & 1) << 1) |
                                          ((lane >> 2) & 1));
                    float vA, vB; unpack2(macc[0], vA, vB);
                    sMi[iA*36 + e] = vA;
                    sMi[iB*36 + e] = vB;
                }
            }
        }
        __syncthreads();

        // ---- GRU cell (GELU new gate), packed col-pairs ----
        {
            const int n  = tid >> 3;
            const int c0 = (tid & 7) << 3;
            ull ar[4], az[4], an_[4], hn_[4];
            #pragma unroll
            for (int o = 0; o < 4; ++o) {
                ull bi_r = *(const ull*)(p.bih + c0 + 2*o);
                ull bh_r = *(const ull*)(p.bhh + c0 + 2*o);
                ull bi_z = *(const ull*)(p.bih + 64 + c0 + 2*o);
                ull bh_z = *(const ull*)(p.bhh + 64 + c0 + 2*o);
                ar[o]  = add2(bi_r, bh_r);
                az[o]  = add2(bi_z, bh_z);
                an_[o] = *(const ull*)(p.bih + 128 + c0 + 2*o);
                hn_[o] = *(const ull*)(p.bhh + 128 + c0 + 2*o);
            }
            const float* mi = sMi + n*36;
            #pragma unroll 2
            for (int k = 0; k < 34; ++k) {
                ull aa = dup2(mi[k]);
                const float* w = p.Wih + k*192;
                ulonglong2 r01 = *(const ulonglong2*)(w + c0);
                ulonglong2 r23 = *(const ulonglong2*)(w + c0 + 4);
                ulonglong2 z01 = *(const ulonglong2*)(w + 64 + c0);
                ulonglong2 z23 = *(const ulonglong2*)(w + 64 + c0 + 4);
                ulonglong2 n01 = *(const ulonglong2*)(w + 128 + c0);
                ulonglong2 n23 = *(const ulonglong2*)(w + 128 + c0 + 4);
                ar[0]=fma2(aa,r01.x,ar[0]); ar[1]=fma2(aa,r01.y,ar[1]);
                ar[2]=fma2(aa,r23.x,ar[2]); ar[3]=fma2(aa,r23.y,ar[3]);
                az[0]=fma2(aa,z01.x,az[0]); az[1]=fma2(aa,z01.y,az[1]);
                az[2]=fma2(aa,z23.x,az[2]); az[3]=fma2(aa,z23.y,az[3]);
                an_[0]=fma2(aa,n01.x,an_[0]); an_[1]=fma2(aa,n01.y,an_[1]);
                an_[2]=fma2(aa,n23.x,an_[2]); an_[3]=fma2(aa,n23.y,an_[3]);
            }
            const float* hv = sH + n*65;
            #pragma unroll 2
            for (int k = 0; k < 64; ++k) {
                ull aa = dup2(hv[k]);
                const float* w = p.Whh + k*192;
                ulonglong2 r01 = *(const ulonglong2*)(w + c0);
                ulonglong2 r23 = *(const ulonglong2*)(w + c0 + 4);
                ulonglong2 z01 = *(const ulonglong2*)(w + 64 + c0);
                ulonglong2 z23 = *(const ulonglong2*)(w + 64 + c0 + 4);
                ulonglong2 n01 = *(const ulonglong2*)(w + 128 + c0);
                ulonglong2 n23 = *(const ulonglong2*)(w + 128 + c0 + 4);
                ar[0]=fma2(aa,r01.x,ar[0]); ar[1]=fma2(aa,r01.y,ar[1]);
                ar[2]=fma2(aa,r23.x,ar[2]); ar[3]=fma2(aa,r23.y,ar[3]);
                az[0]=fma2(aa,z01.x,az[0]); az[1]=fma2(aa,z01.y,az[1]);
                az[2]=fma2(aa,z23.x,az[2]); az[3]=fma2(aa,z23.y,az[3]);
                hn_[0]=fma2(aa,n01.x,hn_[0]); hn_[1]=fma2(aa,n01.y,hn_[1]);
                hn_[2]=fma2(aa,n23.x,hn_[2]); hn_[3]=fma2(aa,n23.y,hn_[3]);
            }
            float hnew[8];
            #pragma unroll
            for (int o = 0; o < 4; ++o) {
                float r0, r1, z0, z1, in0, in1, hn0, hn1;
                unpack2(ar[o], r0, r1);
                unpack2(az[o], z0, z1);
                unpack2(an_[o], in0, in1);
                unpack2(hn_[o], hn0, hn1);
                float rr0 = sigm_f(r0), rr1 = sigm_f(r1);
                float zz0 = sigm_f(z0), zz1 = sigm_f(z1);
                float g0, g1;
                unpack2(gelu2(pack2(fmaf(rr0, hn0, in0), fmaf(rr1, hn1, in1))), g0, g1);
                hnew[2*o]   = (1.0f - zz0) * g0 + zz0 * hv[c0 + 2*o];
                hnew[2*o+1] = (1.0f - zz1) * g1 + zz1 * hv[c0 + 2*o + 1];
            }
            __syncthreads();
            #pragma unroll
            for (int o = 0; o < 8; ++o) sH[n*65 + c0 + o] = hnew[o];
        }
        __syncthreads();

        // ---- node = h @ W3b + b3b  (packed, write transposed into sNT) ----
        {
            const int n = tid >> 3, f0 = (tid & 7) << 2;
            ull a01 = *(const ull*)(p.b3b + f0);
            ull a23 = *(const ull*)(p.b3b + f0 + 2);
            const float* hv = sH + n*65;
            #pragma unroll 4
            for (int k = 0; k < 64; ++k) {
                ull aa = dup2(hv[k]);
                ulonglong2 w2 = *(const ulonglong2*)(p.W3b + k*32 + f0);
                a01 = fma2(aa, w2.x, a01);
                a23 = fma2(aa, w2.y, a23);
            }
            float v0, v1, v2, v3;
            unpack2(a01, v0, v1); unpack2(a23, v2, v3);
            sNT[(f0+0)*33 + n] = v0; sNT[(f0+1)*33 + n] = v1;
            sNT[(f0+2)*33 + n] = v2; sNT[(f0+3)*33 + n] = v3;
        }
        __syncthreads();
    }

    // ---- readout (scratch: bufA=t1, sBase=t2, sProj=t3, sBase=t4) ----
    {   // t1 = node @ W4a + b4a : [32][68]
        const int n = tid >> 3, f0 = (tid & 7) << 3;
        ull acc[4];
        acc[0] = *(const ull*)(p.b4a + f0);
        acc[1] = *(const ull*)(p.b4a + f0 + 2);
        acc[2] = *(const ull*)(p.b4a + f0 + 4);
        acc[3] = *(const ull*)(p.b4a + f0 + 6);
        #pragma unroll 4
        for (int k = 0; k < 32; ++k) {
            ull aa = dup2(sNT[k*33 + n]);
            ulonglong2 w0 = *(const ulonglong2*)(p.W4a + k*64 + f0);
            ulonglong2 w1 = *(const ulonglong2*)(p.W4a + k*64 + f0 + 4);
            acc[0] = fma2(aa, w0.x, acc[0]); acc[1] = fma2(aa, w0.y, acc[1]);
            acc[2] = fma2(aa, w1.x, acc[2]); acc[3] = fma2(aa, w1.y, acc[3]);
        }
        *(ulonglong2*)(bufA + n*68 + f0)     = make_ulonglong2(acc[0], acc[1]);
        *(ulonglong2*)(bufA + n*68 + f0 + 4) = make_ulonglong2(acc[2], acc[3]);
    }
    __syncthreads();
    {   // t2 = t1 @ W4b + b4b : [32][36] into sBase
        const int n = tid >> 3, f0 = (tid & 7) << 2;
        ull a01 = *(const ull*)(p.b4b + f0);
        ull a23 = *(const ull*)(p.b4b + f0 + 2);
        const float* r = bufA + n*68;
        #pragma unroll 4
        for (int k = 0; k < 64; ++k) {
            ull aa = dup2(r[k]);
            ulonglong2 w2 = *(const ulonglong2*)(p.W4b + k*32 + f0);
            a01 = fma2(aa, w2.x, a01);
            a23 = fma2(aa, w2.y, a23);
        }
        *(ull*)(sBase + n*36 + f0)     = a01;
        *(ull*)(sBase + n*36 + f0 + 2) = a23;
    }
    __syncthreads();
    {   // t3 = t2 @ W4c + b4c : [32][36] into sProj
        const int n = tid >> 3, f0 = (tid & 7) << 2;
        ull a01 = *(const ull*)(p.b4c + f0);
        ull a23 = *(const ull*)(p.b4c + f0 + 2);
        const float* r = sBase + n*36;
        #pragma unroll 4
        for (int k = 0; k < 32; ++k) {
            ull aa = dup2(r[k]);
            ulonglong2 w2 = *(const ulonglong2*)(p.W4c + k*32 + f0);
            a01 = fma2(aa, w2.x, a01);
            a23 = fma2(aa, w2.y, a23);
        }
        *(ull*)(sProj + n*36 + f0)     = a01;
        *(ull*)(sProj + n*36 + f0 + 2) = a23;
    }
    __syncthreads();
    {   // t4 = t3 @ W5a + b5a : [32][18] into sBase
        const int n = tid >> 3, f0 = (tid & 7) << 1;
        float a0 = p.b5a[f0], a1 = p.b5a[f0 + 1];
        const float* r = sProj + n*36;
        #pragma unroll 8
        for (int k = 0; k < 32; ++k) {
            float a = r[k];
            a0 += a * p.W5a[k*16 + f0];
            a1 += a * p.W5a[k*16 + f0 + 1];
        }
        sBase[n*18 + f0]     = a0;
        sBase[n*18 + f0 + 1] = a1;
    }
    __syncthreads();
    if (tid < 64) {
        const int n = tid >> 1, col = tid & 1;
        float acc = p.b5b[col];
        const float* r = sBase + n*18;
        #pragma unroll
        for (int k = 0; k < 16; ++k) acc += r[k] * p.W5b[k*2 + col];
        if (col == 0) p.out[b*32 + n] = acc;
        else          p.out[32768 + b*32 + n] = 1.0f / acc;
    }
}

extern "C" void kernel_launch(void* const* d_in, const int* in_sizes, int n_in,
                              void* d_out, int out_size) {
    const int has_iter = (n_in >= 32) ? 1 : 0;
    const int base = has_iter ? 8 : 7;

    GnnParams p;
    p.node0 = (const float*)d_in[0];
    p.edge  = (const float*)d_in[1];
    p.h0    = (const float*)d_in[2];
    p.mean  = (const float*)d_in[3];
    p.vari  = (const float*)d_in[4];
    p.iterp = has_iter ? (const int*)d_in[7] : nullptr;
    p.W1a = (const float*)d_in[base+0];  p.b1a = (const float*)d_in[base+1];
    p.W2a = (const float*)d_in[base+2];  p.b2a = (const float*)d_in[base+3];
    p.W2b = (const float*)d_in[base+4];  p.b2b = (const float*)d_in[base+5];
    p.W2c = (const float*)d_in[base+6];  p.b2c = (const float*)d_in[base+7];
    p.Wih = (const float*)d_in[base+8];  p.Whh = (const float*)d_in[base+9];
    p.bih = (const float*)d_in[base+10]; p.bhh = (const float*)d_in[base+11];
    p.W3b = (const float*)d_in[base+12]; p.b3b = (const float*)d_in[base+13];
    p.W4a = (const float*)d_in[base+14]; p.b4a = (const float*)d_in[base+15];
    p.W4b = (const float*)d_in[base+16]; p.b4b = (const float*)d_in[base+17];
    p.W4c = (const float*)d_in[base+18]; p.b4c = (const float*)d_in[base+19];
    p.W5a = (const float*)d_in[base+20]; p.b5a = (const float*)d_in[base+21];
    p.W5b = (const float*)d_in[base+22]; p.b5b = (const float*)d_in[base+23];
    p.out = (float*)d_out;

    cudaFuncSetAttribute(gnn_kernel,
                         cudaFuncAttributeMaxDynamicSharedMemorySize,
                         SMEM_FLOATS * (int)sizeof(float));
    gnn_kernel<<<1024, NT, SMEM_FLOATS * sizeof(float)>>>(p);
}